// round 15
// baseline (speedup 1.0000x reference)
#include <cuda_runtime.h>
#include <math.h>
#include <stdint.h>

#define BB   4
#define SEQ  2048
#define NH   16
#define DK   64
#define EMB  1024
#define ROWS (BB*SEQ)   // 8192

// Scratch (static device globals — no runtime allocation allowed)
__device__ float g_zqkv[3][ROWS * DK];                   // bottleneck outputs
__device__ float g_qkv[3][(size_t)ROWS * EMB];           // expanded q,k,v  [b*n, H*64]
__device__ float g_att[(size_t)ROWS * EMB];              // attention output pre-proj

// ======================= helpers ===========================================
__device__ __forceinline__ uint32_t tf32cvt(float x) {
    uint32_t r; asm("cvt.rna.tf32.f32 %0, %1;" : "=r"(r) : "f"(x)); return r;
}
__device__ __forceinline__ float tf32f(float x) {
    return __uint_as_float(tf32cvt(x));
}
__device__ __forceinline__ uint32_t smem_u32(const void* p) {
    uint32_t a;
    asm("{ .reg .u64 t; cvta.to.shared.u64 t, %1; cvt.u32.u64 %0, t; }" : "=r"(a) : "l"(p));
    return a;
}
__device__ __forceinline__ void cpa16(uint32_t dst, const void* src) {
    asm volatile("cp.async.cg.shared.global [%0], [%1], 16;" :: "r"(dst), "l"(src));
}
#define CP_COMMIT() asm volatile("cp.async.commit_group;" ::: "memory")
#define CP_WAIT0()  asm volatile("cp.async.wait_group 0;" ::: "memory")

// in-place RNA tf32 conversion of 4 consecutive floats in smem
__device__ __forceinline__ void cvt4_inplace(float* p) {
    float4 v = *(float4*)p;
    *(float4*)p = make_float4(tf32f(v.x), tf32f(v.y), tf32f(v.z), tf32f(v.w));
}

// mma.sync m16n8k8 tf32 (sm_80+ feature; compiles under compute_103)
__device__ __forceinline__ void mma8(float d[4], const uint32_t a[4],
                                     uint32_t b0, uint32_t b1) {
    asm volatile("mma.sync.aligned.m16n8k8.row.col.f32.tf32.tf32.f32 "
        "{%0,%1,%2,%3}, {%4,%5,%6,%7}, {%8,%9}, {%0,%1,%2,%3};"
        : "+f"(d[0]), "+f"(d[1]), "+f"(d[2]), "+f"(d[3])
        : "r"(a[0]), "r"(a[1]), "r"(a[2]), "r"(a[3]), "r"(b0), "r"(b1));
}

// ---------------------------------------------------------------------------
// Kernel 1: FUSED bottleneck projections  zq|zk|zv = z @ [wq|wk|wv]
// grid (128), 256 threads.  CTA output 64 rows x 192 cols; A staged once
// per k-chunk (was 3x), inner loop 48 FFMA per 7 smem loads.
// ---------------------------------------------------------------------------
__global__ void __launch_bounds__(256, 1) k_bottleneck(
    const float* __restrict__ z,
    const float* __restrict__ wq,
    const float* __restrict__ wk,
    const float* __restrict__ wv)
{
    __shared__ __align__(16) float As[64][17];
    __shared__ __align__(16) float Bs[16][3 * 68];

    const int tid = threadIdx.x;
    const int tx = tid & 15, ty = tid >> 4;
    const int row0 = blockIdx.x * 64;

    float acc[3][4][4] = {};

    for (int k0 = 0; k0 < EMB; k0 += 16) {
        {   // A tile 64x16, staged once
            int r = tid >> 2, seg = tid & 3;
            float4 av = *(const float4*)(z + (size_t)(row0 + r) * EMB + k0 + seg * 4);
            As[r][seg*4+0] = av.x; As[r][seg*4+1] = av.y;
            As[r][seg*4+2] = av.z; As[r][seg*4+3] = av.w;
        }
        {   // B tiles 16x64 x3 (w matrices row-major [EMB][64])
            int r = tid >> 4, seg = tid & 15;
            *(float4*)&Bs[r][       seg*4] = *(const float4*)(wq + (size_t)(k0 + r) * DK + seg * 4);
            *(float4*)&Bs[r][ 68 +  seg*4] = *(const float4*)(wk + (size_t)(k0 + r) * DK + seg * 4);
            *(float4*)&Bs[r][136 +  seg*4] = *(const float4*)(wv + (size_t)(k0 + r) * DK + seg * 4);
        }
        __syncthreads();
        #pragma unroll
        for (int k = 0; k < 16; k++) {
            float a0 = As[ty*4+0][k], a1 = As[ty*4+1][k];
            float a2 = As[ty*4+2][k], a3 = As[ty*4+3][k];
            #pragma unroll
            for (int m = 0; m < 3; m++) {
                float4 b4 = *(float4*)&Bs[k][m*68 + tx*4];
                acc[m][0][0] += a0*b4.x; acc[m][0][1] += a0*b4.y; acc[m][0][2] += a0*b4.z; acc[m][0][3] += a0*b4.w;
                acc[m][1][0] += a1*b4.x; acc[m][1][1] += a1*b4.y; acc[m][1][2] += a1*b4.z; acc[m][1][3] += a1*b4.w;
                acc[m][2][0] += a2*b4.x; acc[m][2][1] += a2*b4.y; acc[m][2][2] += a2*b4.z; acc[m][2][3] += a2*b4.w;
                acc[m][3][0] += a3*b4.x; acc[m][3][1] += a3*b4.y; acc[m][3][2] += a3*b4.z; acc[m][3][3] += a3*b4.w;
            }
        }
        __syncthreads();
    }
    #pragma unroll
    for (int m = 0; m < 3; m++)
        #pragma unroll
        for (int i = 0; i < 4; i++)
            *(float4*)&g_zqkv[m][(size_t)(row0 + ty*4 + i) * DK + tx*4] =
                make_float4(acc[m][i][0], acc[m][i][1], acc[m][i][2], acc[m][i][3]);
}

// ---------------------------------------------------------------------------
// Kernel 2: expansion  (fp32 FFMA, 8x4 microtile; A staged once over 4
// B-chunks).  grid (64, 4, 3).
// ---------------------------------------------------------------------------
#define EXP_PITCH 68
#define SMEM_EXP ((128 + 64) * EXP_PITCH * 4)

__global__ void __launch_bounds__(256, 1) k_expand(
    const float* __restrict__ fcq_w, const float* __restrict__ fcq_b,
    const float* __restrict__ fck_w, const float* __restrict__ fck_b,
    const float* __restrict__ fcv_w, const float* __restrict__ fcv_b)
{
    extern __shared__ __align__(16) float sme[];
    float* As = sme;
    float* Bs = sme + 128 * EXP_PITCH;

    const int m = blockIdx.z;
    const float* w    = (m == 0) ? fcq_w : (m == 1) ? fck_w : fcv_w;
    const float* bias = (m == 0) ? fcq_b : (m == 1) ? fck_b : fcv_b;
    const float* in = g_zqkv[m];
    float* out = g_qkv[m];

    const int tid = threadIdx.x;
    const int tx = tid & 15, ty = tid >> 4;
    const int row0 = blockIdx.x * 128;

    #pragma unroll
    for (int i = 0; i < 8; i++) {
        int idx = tid + i * 256;
        int r = idx >> 4, col = (idx & 15) * 4;
        *(float4*)&As[r*EXP_PITCH + col] = *(const float4*)(in + (size_t)(row0 + r) * DK + col);
    }
    {
        int n0 = blockIdx.y * 256;
        #pragma unroll
        for (int i = 0; i < 4; i++) {
            int idx = tid + i * 256;
            int r = idx >> 4, col = (idx & 15) * 4;
            *(float4*)&Bs[r*EXP_PITCH + col] = *(const float4*)(w + (size_t)r * EMB + n0 + col);
        }
    }
    __syncthreads();

    #pragma unroll 1
    for (int nc = 0; nc < 4; nc++) {
        const int n0 = blockIdx.y * 256 + nc * 64;

        float acc[8][4];
        #pragma unroll
        for (int i = 0; i < 8; i++)
            #pragma unroll
            for (int j = 0; j < 4; j++) acc[i][j] = 0.f;

        #pragma unroll 8
        for (int k = 0; k < 64; k++) {
            float4 b4 = *(float4*)&Bs[k*EXP_PITCH + tx*4];
            #pragma unroll
            for (int i = 0; i < 8; i++) {
                float a = As[(ty*8 + i)*EXP_PITCH + k];
                acc[i][0] += a*b4.x; acc[i][1] += a*b4.y;
                acc[i][2] += a*b4.z; acc[i][3] += a*b4.w;
            }
        }

        float4 bi = *(const float4*)(bias + n0 + tx*4);
        #pragma unroll
        for (int i = 0; i < 8; i++)
            *(float4*)&out[(size_t)(row0 + ty*8 + i) * EMB + n0 + tx*4] =
                make_float4(acc[i][0]+bi.x, acc[i][1]+bi.y, acc[i][2]+bi.z, acc[i][3]+bi.w);

        if (nc + 1 < 4) {
            __syncthreads();
            int n1 = blockIdx.y * 256 + (nc + 1) * 64;
            #pragma unroll
            for (int i = 0; i < 4; i++) {
                int idx = tid + i * 256;
                int r = idx >> 4, col = (idx & 15) * 4;
                *(float4*)&Bs[r*EXP_PITCH + col] = *(const float4*)(w + (size_t)r * EMB + n1 + col);
            }
            __syncthreads();
        }
    }
}

// ---------------------------------------------------------------------------
// Kernel 3: flash attention (R13: cp.async double-buffered K/V, in-smem RNA
// convert, __expf on MUFU, 2 CTAs/SM).
// ---------------------------------------------------------------------------
#define PKK 68
#define PKV 72
#define PKP 72
#define OFF_KB 0                             // 2 x [64][68]
#define OFF_V  (2*64*PKK)                    // 2 x [64][72]
#define OFF_P  (2*64*PKK + 2*64*PKV)         // [128][72]
#define SMEM_ATTN ((2*64*PKK + 2*64*PKV + 128*PKP) * 4)   // 108544 B
#define NT (SEQ/64)

__global__ void __launch_bounds__(256, 2) k_attn_mma() {
    extern __shared__ __align__(16) float sm[];
    float* Ps = sm + OFF_P;
    const uint32_t sb = smem_u32(sm);

    const int tid  = threadIdx.x;
    const int warp = tid >> 5, lane = tid & 31;
    const int g = lane >> 2, c = lane & 3;
    const int wr = warp * 16;
    const int b = blockIdx.z, h = blockIdx.y;
    const int q0 = blockIdx.x * 128;

    const float* qp = g_qkv[0] + ((size_t)(b * SEQ + q0)) * EMB + h * DK;
    const float* kp = g_qkv[1] + ((size_t)(b * SEQ)) * EMB + h * DK;
    const float* vp = g_qkv[2] + ((size_t)(b * SEQ)) * EMB + h * DK;

    const int sr = tid >> 4, sc4 = (tid & 15) * 4;

    // ---- prologue: async K(0)+V(0); stage Q; extract qa; convert; issue (1) ----
    #pragma unroll
    for (int i = 0; i < 4; i++) {
        int r = sr + i * 16;
        cpa16(sb + (uint32_t)(OFF_KB + r*PKK + sc4) * 4, kp + (size_t)r * EMB + sc4);
        cpa16(sb + (uint32_t)(OFF_V  + r*PKV + sc4) * 4, vp + (size_t)r * EMB + sc4);
    }
    CP_COMMIT();

    #pragma unroll
    for (int i = 0; i < 8; i++) {
        int idx = tid + i * 256;
        int r = idx >> 4, col = (idx & 15) * 4;
        *(float4*)&Ps[r*PKP + col] = *(const float4*)(qp + (size_t)r * EMB + col);
    }
    __syncthreads();

    uint32_t qa[8][4];
    #pragma unroll
    for (int k = 0; k < 8; k++) {
        qa[k][0] = tf32cvt(Ps[(wr + g    )*PKP + k*8 + c    ]);
        qa[k][1] = tf32cvt(Ps[(wr + 8 + g)*PKP + k*8 + c    ]);
        qa[k][2] = tf32cvt(Ps[(wr + g    )*PKP + k*8 + c + 4]);
        qa[k][3] = tf32cvt(Ps[(wr + 8 + g)*PKP + k*8 + c + 4]);
    }
    CP_WAIT0();
    __syncthreads();     // K(0)/V(0) raw visible; qa extraction done

    #pragma unroll
    for (int i = 0; i < 4; i++) {
        cvt4_inplace(sm + OFF_KB + (sr + i*16)*PKK + sc4);
        cvt4_inplace(sm + OFF_V  + (sr + i*16)*PKV + sc4);
    }
    // issue tile 1 into buffer 1 (no conflict with buffer 0)
    {
        const float* kn = kp + (size_t)64 * EMB;
        const float* vn = vp + (size_t)64 * EMB;
        #pragma unroll
        for (int i = 0; i < 4; i++) {
            int r = sr + i * 16;
            cpa16(sb + (uint32_t)(OFF_KB + 64*PKK + r*PKK + sc4) * 4, kn + (size_t)r * EMB + sc4);
            cpa16(sb + (uint32_t)(OFF_V  + 64*PKV + r*PKV + sc4) * 4, vn + (size_t)r * EMB + sc4);
        }
        CP_COMMIT();
    }
    __syncthreads();     // converted K(0)/V(0) visible

    float oacc[8][4];
    #pragma unroll
    for (int n = 0; n < 8; n++)
        #pragma unroll
        for (int e = 0; e < 4; e++) oacc[n][e] = 0.f;
    float l0 = 0.f, l1 = 0.f;

    const int p0 = (c & 1) * 4 + (c >> 1);

    #pragma unroll 1
    for (int t = 0; t < NT; t++) {
        const float* Kcur = sm + OFF_KB + (t & 1) * 64 * PKK;
        const float* Vcur = sm + OFF_V  + (t & 1) * 64 * PKV;

        // ---- S = Q K^T ----
        float sacc[8][4];
        #pragma unroll
        for (int n = 0; n < 8; n++)
            #pragma unroll
            for (int e = 0; e < 4; e++) sacc[n][e] = 0.f;
        #pragma unroll
        for (int k = 0; k < 8; k++) {
            #pragma unroll
            for (int n = 0; n < 8; n++) {
                uint32_t b0 = __float_as_uint(Kcur[(n*8 + g)*PKK + k*8 + c    ]);
                uint32_t b1 = __float_as_uint(Kcur[(n*8 + g)*PKK + k*8 + c + 4]);
                mma8(sacc[n], qa[k], b0, b1);
            }
        }

        // ---- P = exp(S/8) via MUFU; RNA tf32 pair-permuted store ----
        #pragma unroll
        for (int n = 0; n < 8; n++) {
            float e0 = __expf(sacc[n][0] * 0.125f);
            float e1 = __expf(sacc[n][1] * 0.125f);
            float e2 = __expf(sacc[n][2] * 0.125f);
            float e3 = __expf(sacc[n][3] * 0.125f);
            l0 += e0 + e1;
            l1 += e2 + e3;
            Ps[(wr + g    )*PKP + n*8 + p0    ] = tf32f(e0);
            Ps[(wr + g    )*PKP + n*8 + p0 + 2] = tf32f(e1);
            Ps[(wr + 8 + g)*PKP + n*8 + p0    ] = tf32f(e2);
            Ps[(wr + 8 + g)*PKP + n*8 + p0 + 2] = tf32f(e3);
        }
        __syncwarp();

        // ---- O += P V ----
        #pragma unroll
        for (int k = 0; k < 8; k++) {
            float2 pA = *(const float2*)&Ps[(wr + g    )*PKP + k*8 + 2*c];
            float2 pB = *(const float2*)&Ps[(wr + 8 + g)*PKP + k*8 + 2*c];
            uint32_t a[4] = { __float_as_uint(pA.x), __float_as_uint(pB.x),
                              __float_as_uint(pA.y), __float_as_uint(pB.y) };
            #pragma unroll
            for (int n = 0; n < 8; n++) {
                uint32_t b0 = __float_as_uint(Vcur[(k*8 + c    )*PKV + n*8 + g]);
                uint32_t b1 = __float_as_uint(Vcur[(k*8 + c + 4)*PKV + n*8 + g]);
                mma8(oacc[n], a, b0, b1);
            }
        }

        // ---- pipeline turn: land (t+1), convert, issue (t+2) ----
        if (t + 1 < NT) {
            float* Knxt = sm + OFF_KB + ((t + 1) & 1) * 64 * PKK;
            float* Vnxt = sm + OFF_V  + ((t + 1) & 1) * 64 * PKV;
            CP_WAIT0();
            __syncthreads();   // (t+1) raw visible; all reads of (t) buffers done
            #pragma unroll
            for (int i = 0; i < 4; i++) {
                cvt4_inplace(&Knxt[(sr + i*16)*PKK + sc4]);
                cvt4_inplace(&Vnxt[(sr + i*16)*PKV + sc4]);
            }
            if (t + 2 < NT) {
                const float* kn = kp + (size_t)(t + 2) * 64 * EMB;
                const float* vn = vp + (size_t)(t + 2) * 64 * EMB;
                uint32_t kb = (uint32_t)(OFF_KB + (t & 1) * 64 * PKK);
                uint32_t vb = (uint32_t)(OFF_V  + (t & 1) * 64 * PKV);
                #pragma unroll
                for (int i = 0; i < 4; i++) {
                    int r = sr + i * 16;
                    cpa16(sb + (kb + r*PKK + sc4) * 4, kn + (size_t)r * EMB + sc4);
                    cpa16(sb + (vb + r*PKV + sc4) * 4, vn + (size_t)r * EMB + sc4);
                }
                CP_COMMIT();
            }
            __syncthreads();   // converted (t+1) visible
        }
    }

    // ---- epilogue ----
    l0 += __shfl_xor_sync(0xffffffffu, l0, 1);
    l0 += __shfl_xor_sync(0xffffffffu, l0, 2);
    l1 += __shfl_xor_sync(0xffffffffu, l1, 1);
    l1 += __shfl_xor_sync(0xffffffffu, l1, 2);
    float inv0 = 1.f / l0, inv1 = 1.f / l1;

    float* op0 = g_att + ((size_t)(b * SEQ + q0 + wr + g    )) * EMB + h * DK;
    float* op1 = g_att + ((size_t)(b * SEQ + q0 + wr + 8 + g)) * EMB + h * DK;
    #pragma unroll
    for (int n = 0; n < 8; n++) {
        int colb = n*8 + 2*c;
        *(float2*)&op0[colb] = make_float2(oacc[n][0] * inv0, oacc[n][1] * inv0);
        *(float2*)&op1[colb] = make_float2(oacc[n][2] * inv1, oacc[n][3] * inv1);
    }
}

// ---------------------------------------------------------------------------
// Kernel 4: output projection via tf32 mma, register-prefetch pipelined (R9).
// ---------------------------------------------------------------------------
#define GP_A 68
#define GP_W 72
#define SMEM_GEMM ((128*GP_A + 64*GP_W) * 4)
#define KCH 16

__global__ void __launch_bounds__(256, 1) k_outproj_mma(
    const float* __restrict__ fco_w, const float* __restrict__ fco_b,
    float* __restrict__ out)
{
    extern __shared__ __align__(16) float smg[];
    float* As = smg;
    float* Ws = smg + 128 * GP_A;

    const int tid  = threadIdx.x;
    const int warp = tid >> 5, lane = tid & 31;
    const int g = lane >> 2, c = lane & 3;
    const int wr = warp * 16;
    const int row0 = blockIdx.x * 128, n0 = blockIdx.y * 64;

    const float* A = g_att;
    const float* W = fco_w;

    float4 pa[8], pw[4];

    #pragma unroll
    for (int i = 0; i < 8; i++) {
        int idx = tid + i * 256;
        int r = idx >> 4, col = (idx & 15) * 4;
        pa[i] = *(const float4*)(A + (size_t)(row0 + r) * EMB + col);
    }
    #pragma unroll
    for (int i = 0; i < 4; i++) {
        int idx = tid + i * 256;
        int r = idx >> 4, col = (idx & 15) * 4;
        pw[i] = *(const float4*)(W + (size_t)r * EMB + n0 + col);
    }

    float acc[8][4];
    #pragma unroll
    for (int nf = 0; nf < 8; nf++)
        #pragma unroll
        for (int e = 0; e < 4; e++) acc[nf][e] = 0.f;

    #pragma unroll 1
    for (int kc = 0; kc < KCH; kc++) {
        #pragma unroll
        for (int i = 0; i < 8; i++) {
            int idx = tid + i * 256;
            int r = idx >> 4, col = (idx & 15) * 4;
            *(float4*)&As[r*GP_A + col] =
                make_float4(tf32f(pa[i].x), tf32f(pa[i].y), tf32f(pa[i].z), tf32f(pa[i].w));
        }
        #pragma unroll
        for (int i = 0; i < 4; i++) {
            int idx = tid + i * 256;
            int r = idx >> 4, col = (idx & 15) * 4;
            *(float4*)&Ws[r*GP_W + col] =
                make_float4(tf32f(pw[i].x), tf32f(pw[i].y), tf32f(pw[i].z), tf32f(pw[i].w));
        }
        __syncthreads();

        if (kc + 1 < KCH) {
            const float* Ak = A + (kc + 1) * 64;
            const float* Wk = W + (size_t)((kc + 1) * 64) * EMB;
            #pragma unroll
            for (int i = 0; i < 8; i++) {
                int idx = tid + i * 256;
                int r = idx >> 4, col = (idx & 15) * 4;
                pa[i] = *(const float4*)(Ak + (size_t)(row0 + r) * EMB + col);
            }
            #pragma unroll
            for (int i = 0; i < 4; i++) {
                int idx = tid + i * 256;
                int r = idx >> 4, col = (idx & 15) * 4;
                pw[i] = *(const float4*)(Wk + (size_t)r * EMB + n0 + col);
            }
        }

        #pragma unroll
        for (int ks = 0; ks < 8; ks++) {
            uint32_t a[4];
            a[0] = __float_as_uint(As[(wr + g    )*GP_A + ks*8 + c    ]);
            a[1] = __float_as_uint(As[(wr + 8 + g)*GP_A + ks*8 + c    ]);
            a[2] = __float_as_uint(As[(wr + g    )*GP_A + ks*8 + c + 4]);
            a[3] = __float_as_uint(As[(wr + 8 + g)*GP_A + ks*8 + c + 4]);
            #pragma unroll
            for (int nf = 0; nf < 8; nf++) {
                uint32_t b0 = __float_as_uint(Ws[(ks*8 + c    )*GP_W + nf*8 + g]);
                uint32_t b1 = __float_as_uint(Ws[(ks*8 + c + 4)*GP_W + nf*8 + g]);
                mma8(acc[nf], a, b0, b1);
            }
        }
        __syncthreads();
    }

    #pragma unroll
    for (int nf = 0; nf < 8; nf++) {
        int col = n0 + nf*8 + 2*c;
        float bx = fco_b[col], by = fco_b[col + 1];
        *(float2*)&out[(size_t)(row0 + wr + g    ) * EMB + col] =
            make_float2(acc[nf][0] + bx, acc[nf][1] + by);
        *(float2*)&out[(size_t)(row0 + wr + 8 + g) * EMB + col] =
            make_float2(acc[nf][2] + bx, acc[nf][3] + by);
    }
}

// ---------------------------------------------------------------------------
extern "C" void kernel_launch(void* const* d_in, const int* in_sizes, int n_in,
                              void* d_out, int out_size) {
    const float* z     = (const float*)d_in[0];
    const float* wq    = (const float*)d_in[1];
    const float* wk    = (const float*)d_in[2];
    const float* wv    = (const float*)d_in[3];
    const float* fcq_w = (const float*)d_in[4];
    const float* fcq_b = (const float*)d_in[5];
    const float* fck_w = (const float*)d_in[6];
    const float* fck_b = (const float*)d_in[7];
    const float* fcv_w = (const float*)d_in[8];
    const float* fcv_b = (const float*)d_in[9];
    const float* fco_w = (const float*)d_in[10];
    const float* fco_b = (const float*)d_in[11];
    float* out = (float*)d_out;

    static bool attr_set = false;
    if (!attr_set) {
        cudaFuncSetAttribute(k_attn_mma,    cudaFuncAttributeMaxDynamicSharedMemorySize, SMEM_ATTN);
        cudaFuncSetAttribute(k_expand,      cudaFuncAttributeMaxDynamicSharedMemorySize, SMEM_EXP);
        cudaFuncSetAttribute(k_outproj_mma, cudaFuncAttributeMaxDynamicSharedMemorySize, SMEM_GEMM);
        attr_set = true;
    }

    k_bottleneck<<<dim3(ROWS/64), 256>>>(z, wq, wk, wv);
    k_expand<<<dim3(ROWS/128, 4, 3), 256, SMEM_EXP>>>(
        fcq_w, fcq_b, fck_w, fck_b, fcv_w, fcv_b);
    k_attn_mma<<<dim3(SEQ/128, NH, BB), 256, SMEM_ATTN>>>();
    k_outproj_mma<<<dim3(ROWS/128, EMB/64), 256, SMEM_GEMM>>>(fco_w, fco_b, out);
}

// round 16
// speedup vs baseline: 1.5593x; 1.5593x over previous
#include <cuda_runtime.h>
#include <math.h>
#include <stdint.h>

#define BB   4
#define SEQ  2048
#define NH   16
#define DK   64
#define EMB  1024
#define ROWS (BB*SEQ)   // 8192

// Scratch (static device globals — no runtime allocation allowed)
__device__ float g_zqkv[3][ROWS * DK];                   // bottleneck outputs
__device__ float g_qkv[3][(size_t)ROWS * EMB];           // expanded q,k,v  [b*n, H*64]
__device__ float g_att[(size_t)ROWS * EMB];              // attention output pre-proj

// ======================= helpers ===========================================
__device__ __forceinline__ uint32_t tf32cvt(float x) {
    uint32_t r; asm("cvt.rna.tf32.f32 %0, %1;" : "=r"(r) : "f"(x)); return r;
}
__device__ __forceinline__ float tf32f(float x) {
    return __uint_as_float(tf32cvt(x));
}
__device__ __forceinline__ uint32_t smem_u32(const void* p) {
    uint32_t a;
    asm("{ .reg .u64 t; cvta.to.shared.u64 t, %1; cvt.u32.u64 %0, t; }" : "=r"(a) : "l"(p));
    return a;
}
__device__ __forceinline__ void cpa16(uint32_t dst, const void* src) {
    asm volatile("cp.async.cg.shared.global [%0], [%1], 16;" :: "r"(dst), "l"(src));
}
#define CP_COMMIT() asm volatile("cp.async.commit_group;" ::: "memory")
#define CP_WAIT0()  asm volatile("cp.async.wait_group 0;" ::: "memory")

// in-place RNA tf32 conversion of 4 consecutive floats in smem
__device__ __forceinline__ void cvt4_inplace(float* p) {
    float4 v = *(float4*)p;
    *(float4*)p = make_float4(tf32f(v.x), tf32f(v.y), tf32f(v.z), tf32f(v.w));
}

// mma.sync m16n8k8 tf32 (sm_80+ feature; compiles under compute_103)
__device__ __forceinline__ void mma8(float d[4], const uint32_t a[4],
                                     uint32_t b0, uint32_t b1) {
    asm volatile("mma.sync.aligned.m16n8k8.row.col.f32.tf32.tf32.f32 "
        "{%0,%1,%2,%3}, {%4,%5,%6,%7}, {%8,%9}, {%0,%1,%2,%3};"
        : "+f"(d[0]), "+f"(d[1]), "+f"(d[2]), "+f"(d[3])
        : "r"(a[0]), "r"(a[1]), "r"(a[2]), "r"(a[3]), "r"(b0), "r"(b1));
}

// ---------------------------------------------------------------------------
// Kernel 1: fused bottleneck projections   zq/zk/zv = z @ {wq,wk,wv}  (fp32)
// grid (128, 3), 256 threads, 64x64 tile, BK=16, 4x4 microtile.
// ---------------------------------------------------------------------------
__global__ void k_bottleneck(const float* __restrict__ z,
                             const float* __restrict__ wq,
                             const float* __restrict__ wk,
                             const float* __restrict__ wv) {
    __shared__ __align__(16) float As[64][17];
    __shared__ __align__(16) float Bs[16][68];
    const float* w = (blockIdx.y == 0) ? wq : (blockIdx.y == 1) ? wk : wv;
    float* out = g_zqkv[blockIdx.y];

    const int tid = threadIdx.x;
    const int tx = tid & 15, ty = tid >> 4;
    const int row0 = blockIdx.x * 64;

    float acc[4][4] = {};

    for (int k0 = 0; k0 < EMB; k0 += 16) {
        {
            int r = tid >> 2, seg = tid & 3;
            float4 av = *(const float4*)(z + (size_t)(row0 + r) * EMB + k0 + seg * 4);
            As[r][seg*4+0] = av.x; As[r][seg*4+1] = av.y;
            As[r][seg*4+2] = av.z; As[r][seg*4+3] = av.w;
        }
        {
            int r = tid >> 4, seg = tid & 15;
            *(float4*)&Bs[r][seg*4] = *(const float4*)(w + (size_t)(k0 + r) * DK + seg * 4);
        }
        __syncthreads();
        #pragma unroll
        for (int k = 0; k < 16; k++) {
            float a0 = As[ty*4+0][k], a1 = As[ty*4+1][k];
            float a2 = As[ty*4+2][k], a3 = As[ty*4+3][k];
            float4 b4 = *(float4*)&Bs[k][tx*4];
            acc[0][0] += a0*b4.x; acc[0][1] += a0*b4.y; acc[0][2] += a0*b4.z; acc[0][3] += a0*b4.w;
            acc[1][0] += a1*b4.x; acc[1][1] += a1*b4.y; acc[1][2] += a1*b4.z; acc[1][3] += a1*b4.w;
            acc[2][0] += a2*b4.x; acc[2][1] += a2*b4.y; acc[2][2] += a2*b4.z; acc[2][3] += a2*b4.w;
            acc[3][0] += a3*b4.x; acc[3][1] += a3*b4.y; acc[3][2] += a3*b4.z; acc[3][3] += a3*b4.w;
        }
        __syncthreads();
    }
    #pragma unroll
    for (int i = 0; i < 4; i++)
        #pragma unroll
        for (int j = 0; j < 4; j++)
            out[(size_t)(row0 + ty*4 + i) * DK + tx*4 + j] = acc[i][j];
}

// ---------------------------------------------------------------------------
// Kernel 2: expansion  (fp32 FFMA, 8x4 microtile; A staged once over 4
// B-chunks).  grid (64, 4, 3).
// ---------------------------------------------------------------------------
#define EXP_PITCH 68
#define SMEM_EXP ((128 + 64) * EXP_PITCH * 4)

__global__ void __launch_bounds__(256, 1) k_expand(
    const float* __restrict__ fcq_w, const float* __restrict__ fcq_b,
    const float* __restrict__ fck_w, const float* __restrict__ fck_b,
    const float* __restrict__ fcv_w, const float* __restrict__ fcv_b)
{
    extern __shared__ __align__(16) float sme[];
    float* As = sme;
    float* Bs = sme + 128 * EXP_PITCH;

    const int m = blockIdx.z;
    const float* w    = (m == 0) ? fcq_w : (m == 1) ? fck_w : fcv_w;
    const float* bias = (m == 0) ? fcq_b : (m == 1) ? fck_b : fcv_b;
    const float* in = g_zqkv[m];
    float* out = g_qkv[m];

    const int tid = threadIdx.x;
    const int tx = tid & 15, ty = tid >> 4;
    const int row0 = blockIdx.x * 128;

    #pragma unroll
    for (int i = 0; i < 8; i++) {
        int idx = tid + i * 256;
        int r = idx >> 4, col = (idx & 15) * 4;
        *(float4*)&As[r*EXP_PITCH + col] = *(const float4*)(in + (size_t)(row0 + r) * DK + col);
    }
    {
        int n0 = blockIdx.y * 256;
        #pragma unroll
        for (int i = 0; i < 4; i++) {
            int idx = tid + i * 256;
            int r = idx >> 4, col = (idx & 15) * 4;
            *(float4*)&Bs[r*EXP_PITCH + col] = *(const float4*)(w + (size_t)r * EMB + n0 + col);
        }
    }
    __syncthreads();

    #pragma unroll 1
    for (int nc = 0; nc < 4; nc++) {
        const int n0 = blockIdx.y * 256 + nc * 64;

        float acc[8][4];
        #pragma unroll
        for (int i = 0; i < 8; i++)
            #pragma unroll
            for (int j = 0; j < 4; j++) acc[i][j] = 0.f;

        #pragma unroll 8
        for (int k = 0; k < 64; k++) {
            float4 b4 = *(float4*)&Bs[k*EXP_PITCH + tx*4];
            #pragma unroll
            for (int i = 0; i < 8; i++) {
                float a = As[(ty*8 + i)*EXP_PITCH + k];
                acc[i][0] += a*b4.x; acc[i][1] += a*b4.y;
                acc[i][2] += a*b4.z; acc[i][3] += a*b4.w;
            }
        }

        float4 bi = *(const float4*)(bias + n0 + tx*4);
        #pragma unroll
        for (int i = 0; i < 8; i++)
            *(float4*)&out[(size_t)(row0 + ty*8 + i) * EMB + n0 + tx*4] =
                make_float4(acc[i][0]+bi.x, acc[i][1]+bi.y, acc[i][2]+bi.z, acc[i][3]+bi.w);

        if (nc + 1 < 4) {
            __syncthreads();
            int n1 = blockIdx.y * 256 + (nc + 1) * 64;
            #pragma unroll
            for (int i = 0; i < 4; i++) {
                int idx = tid + i * 256;
                int r = idx >> 4, col = (idx & 15) * 4;
                *(float4*)&Bs[r*EXP_PITCH + col] = *(const float4*)(w + (size_t)r * EMB + n1 + col);
            }
            __syncthreads();
        }
    }
}

// ---------------------------------------------------------------------------
// Kernel 3: flash attention (cp.async double-buffered K/V, in-smem RNA
// convert, __expf on MUFU, 2 CTAs/SM).
// ---------------------------------------------------------------------------
#define PKK 68
#define PKV 72
#define PKP 72
#define OFF_KB 0                             // 2 x [64][68]
#define OFF_V  (2*64*PKK)                    // 2 x [64][72]
#define OFF_P  (2*64*PKK + 2*64*PKV)         // [128][72]
#define SMEM_ATTN ((2*64*PKK + 2*64*PKV + 128*PKP) * 4)   // 108544 B
#define NT (SEQ/64)

__global__ void __launch_bounds__(256, 2) k_attn_mma() {
    extern __shared__ __align__(16) float sm[];
    float* Ps = sm + OFF_P;
    const uint32_t sb = smem_u32(sm);

    const int tid  = threadIdx.x;
    const int warp = tid >> 5, lane = tid & 31;
    const int g = lane >> 2, c = lane & 3;
    const int wr = warp * 16;
    const int b = blockIdx.z, h = blockIdx.y;
    const int q0 = blockIdx.x * 128;

    const float* qp = g_qkv[0] + ((size_t)(b * SEQ + q0)) * EMB + h * DK;
    const float* kp = g_qkv[1] + ((size_t)(b * SEQ)) * EMB + h * DK;
    const float* vp = g_qkv[2] + ((size_t)(b * SEQ)) * EMB + h * DK;

    const int sr = tid >> 4, sc4 = (tid & 15) * 4;

    // ---- prologue: async K(0)+V(0); stage Q; extract qa; convert; issue (1) ----
    #pragma unroll
    for (int i = 0; i < 4; i++) {
        int r = sr + i * 16;
        cpa16(sb + (uint32_t)(OFF_KB + r*PKK + sc4) * 4, kp + (size_t)r * EMB + sc4);
        cpa16(sb + (uint32_t)(OFF_V  + r*PKV + sc4) * 4, vp + (size_t)r * EMB + sc4);
    }
    CP_COMMIT();

    #pragma unroll
    for (int i = 0; i < 8; i++) {
        int idx = tid + i * 256;
        int r = idx >> 4, col = (idx & 15) * 4;
        *(float4*)&Ps[r*PKP + col] = *(const float4*)(qp + (size_t)r * EMB + col);
    }
    __syncthreads();

    uint32_t qa[8][4];
    #pragma unroll
    for (int k = 0; k < 8; k++) {
        qa[k][0] = tf32cvt(Ps[(wr + g    )*PKP + k*8 + c    ]);
        qa[k][1] = tf32cvt(Ps[(wr + 8 + g)*PKP + k*8 + c    ]);
        qa[k][2] = tf32cvt(Ps[(wr + g    )*PKP + k*8 + c + 4]);
        qa[k][3] = tf32cvt(Ps[(wr + 8 + g)*PKP + k*8 + c + 4]);
    }
    CP_WAIT0();
    __syncthreads();     // K(0)/V(0) raw visible; qa extraction done

    #pragma unroll
    for (int i = 0; i < 4; i++) {
        cvt4_inplace(sm + OFF_KB + (sr + i*16)*PKK + sc4);
        cvt4_inplace(sm + OFF_V  + (sr + i*16)*PKV + sc4);
    }
    // issue tile 1 into buffer 1 (no conflict with buffer 0)
    {
        const float* kn = kp + (size_t)64 * EMB;
        const float* vn = vp + (size_t)64 * EMB;
        #pragma unroll
        for (int i = 0; i < 4; i++) {
            int r = sr + i * 16;
            cpa16(sb + (uint32_t)(OFF_KB + 64*PKK + r*PKK + sc4) * 4, kn + (size_t)r * EMB + sc4);
            cpa16(sb + (uint32_t)(OFF_V  + 64*PKV + r*PKV + sc4) * 4, vn + (size_t)r * EMB + sc4);
        }
        CP_COMMIT();
    }
    __syncthreads();     // converted K(0)/V(0) visible

    float oacc[8][4];
    #pragma unroll
    for (int n = 0; n < 8; n++)
        #pragma unroll
        for (int e = 0; e < 4; e++) oacc[n][e] = 0.f;
    float l0 = 0.f, l1 = 0.f;

    const int p0 = (c & 1) * 4 + (c >> 1);

    #pragma unroll 1
    for (int t = 0; t < NT; t++) {
        const float* Kcur = sm + OFF_KB + (t & 1) * 64 * PKK;
        const float* Vcur = sm + OFF_V  + (t & 1) * 64 * PKV;

        // ---- S = Q K^T ----
        float sacc[8][4];
        #pragma unroll
        for (int n = 0; n < 8; n++)
            #pragma unroll
            for (int e = 0; e < 4; e++) sacc[n][e] = 0.f;
        #pragma unroll
        for (int k = 0; k < 8; k++) {
            #pragma unroll
            for (int n = 0; n < 8; n++) {
                uint32_t b0 = __float_as_uint(Kcur[(n*8 + g)*PKK + k*8 + c    ]);
                uint32_t b1 = __float_as_uint(Kcur[(n*8 + g)*PKK + k*8 + c + 4]);
                mma8(sacc[n], qa[k], b0, b1);
            }
        }

        // ---- P = exp(S/8) via MUFU; RNA tf32 pair-permuted store ----
        #pragma unroll
        for (int n = 0; n < 8; n++) {
            float e0 = __expf(sacc[n][0] * 0.125f);
            float e1 = __expf(sacc[n][1] * 0.125f);
            float e2 = __expf(sacc[n][2] * 0.125f);
            float e3 = __expf(sacc[n][3] * 0.125f);
            l0 += e0 + e1;
            l1 += e2 + e3;
            Ps[(wr + g    )*PKP + n*8 + p0    ] = tf32f(e0);
            Ps[(wr + g    )*PKP + n*8 + p0 + 2] = tf32f(e1);
            Ps[(wr + 8 + g)*PKP + n*8 + p0    ] = tf32f(e2);
            Ps[(wr + 8 + g)*PKP + n*8 + p0 + 2] = tf32f(e3);
        }
        __syncwarp();

        // ---- O += P V ----
        #pragma unroll
        for (int k = 0; k < 8; k++) {
            float2 pA = *(const float2*)&Ps[(wr + g    )*PKP + k*8 + 2*c];
            float2 pB = *(const float2*)&Ps[(wr + 8 + g)*PKP + k*8 + 2*c];
            uint32_t a[4] = { __float_as_uint(pA.x), __float_as_uint(pB.x),
                              __float_as_uint(pA.y), __float_as_uint(pB.y) };
            #pragma unroll
            for (int n = 0; n < 8; n++) {
                uint32_t b0 = __float_as_uint(Vcur[(k*8 + c    )*PKV + n*8 + g]);
                uint32_t b1 = __float_as_uint(Vcur[(k*8 + c + 4)*PKV + n*8 + g]);
                mma8(oacc[n], a, b0, b1);
            }
        }

        // ---- pipeline turn: land (t+1), convert, issue (t+2) ----
        if (t + 1 < NT) {
            float* Knxt = sm + OFF_KB + ((t + 1) & 1) * 64 * PKK;
            float* Vnxt = sm + OFF_V  + ((t + 1) & 1) * 64 * PKV;
            CP_WAIT0();
            __syncthreads();   // (t+1) raw visible; all reads of (t) buffers done
            #pragma unroll
            for (int i = 0; i < 4; i++) {
                cvt4_inplace(&Knxt[(sr + i*16)*PKK + sc4]);
                cvt4_inplace(&Vnxt[(sr + i*16)*PKV + sc4]);
            }
            if (t + 2 < NT) {
                const float* kn = kp + (size_t)(t + 2) * 64 * EMB;
                const float* vn = vp + (size_t)(t + 2) * 64 * EMB;
                uint32_t kb = (uint32_t)(OFF_KB + (t & 1) * 64 * PKK);
                uint32_t vb = (uint32_t)(OFF_V  + (t & 1) * 64 * PKV);
                #pragma unroll
                for (int i = 0; i < 4; i++) {
                    int r = sr + i * 16;
                    cpa16(sb + (kb + r*PKK + sc4) * 4, kn + (size_t)r * EMB + sc4);
                    cpa16(sb + (vb + r*PKV + sc4) * 4, vn + (size_t)r * EMB + sc4);
                }
                CP_COMMIT();
            }
            __syncthreads();   // converted (t+1) visible
        }
    }

    // ---- epilogue ----
    l0 += __shfl_xor_sync(0xffffffffu, l0, 1);
    l0 += __shfl_xor_sync(0xffffffffu, l0, 2);
    l1 += __shfl_xor_sync(0xffffffffu, l1, 1);
    l1 += __shfl_xor_sync(0xffffffffu, l1, 2);
    float inv0 = 1.f / l0, inv1 = 1.f / l1;

    float* op0 = g_att + ((size_t)(b * SEQ + q0 + wr + g    )) * EMB + h * DK;
    float* op1 = g_att + ((size_t)(b * SEQ + q0 + wr + 8 + g)) * EMB + h * DK;
    #pragma unroll
    for (int n = 0; n < 8; n++) {
        int colb = n*8 + 2*c;
        *(float2*)&op0[colb] = make_float2(oacc[n][0] * inv0, oacc[n][1] * inv0);
        *(float2*)&op1[colb] = make_float2(oacc[n][2] * inv1, oacc[n][3] * inv1);
    }
}

// ---------------------------------------------------------------------------
// Kernel 4: output projection via tf32 mma, register-prefetch pipelined.
// ---------------------------------------------------------------------------
#define GP_A 68
#define GP_W 72
#define SMEM_GEMM ((128*GP_A + 64*GP_W) * 4)
#define KCH 16

__global__ void __launch_bounds__(256, 1) k_outproj_mma(
    const float* __restrict__ fco_w, const float* __restrict__ fco_b,
    float* __restrict__ out)
{
    extern __shared__ __align__(16) float smg[];
    float* As = smg;
    float* Ws = smg + 128 * GP_A;

    const int tid  = threadIdx.x;
    const int warp = tid >> 5, lane = tid & 31;
    const int g = lane >> 2, c = lane & 3;
    const int wr = warp * 16;
    const int row0 = blockIdx.x * 128, n0 = blockIdx.y * 64;

    const float* A = g_att;
    const float* W = fco_w;

    float4 pa[8], pw[4];

    #pragma unroll
    for (int i = 0; i < 8; i++) {
        int idx = tid + i * 256;
        int r = idx >> 4, col = (idx & 15) * 4;
        pa[i] = *(const float4*)(A + (size_t)(row0 + r) * EMB + col);
    }
    #pragma unroll
    for (int i = 0; i < 4; i++) {
        int idx = tid + i * 256;
        int r = idx >> 4, col = (idx & 15) * 4;
        pw[i] = *(const float4*)(W + (size_t)r * EMB + n0 + col);
    }

    float acc[8][4];
    #pragma unroll
    for (int nf = 0; nf < 8; nf++)
        #pragma unroll
        for (int e = 0; e < 4; e++) acc[nf][e] = 0.f;

    #pragma unroll 1
    for (int kc = 0; kc < KCH; kc++) {
        #pragma unroll
        for (int i = 0; i < 8; i++) {
            int idx = tid + i * 256;
            int r = idx >> 4, col = (idx & 15) * 4;
            *(float4*)&As[r*GP_A + col] =
                make_float4(tf32f(pa[i].x), tf32f(pa[i].y), tf32f(pa[i].z), tf32f(pa[i].w));
        }
        #pragma unroll
        for (int i = 0; i < 4; i++) {
            int idx = tid + i * 256;
            int r = idx >> 4, col = (idx & 15) * 4;
            *(float4*)&Ws[r*GP_W + col] =
                make_float4(tf32f(pw[i].x), tf32f(pw[i].y), tf32f(pw[i].z), tf32f(pw[i].w));
        }
        __syncthreads();

        if (kc + 1 < KCH) {
            const float* Ak = A + (kc + 1) * 64;
            const float* Wk = W + (size_t)((kc + 1) * 64) * EMB;
            #pragma unroll
            for (int i = 0; i < 8; i++) {
                int idx = tid + i * 256;
                int r = idx >> 4, col = (idx & 15) * 4;
                pa[i] = *(const float4*)(Ak + (size_t)(row0 + r) * EMB + col);
            }
            #pragma unroll
            for (int i = 0; i < 4; i++) {
                int idx = tid + i * 256;
                int r = idx >> 4, col = (idx & 15) * 4;
                pw[i] = *(const float4*)(Wk + (size_t)r * EMB + n0 + col);
            }
        }

        #pragma unroll
        for (int ks = 0; ks < 8; ks++) {
            uint32_t a[4];
            a[0] = __float_as_uint(As[(wr + g    )*GP_A + ks*8 + c    ]);
            a[1] = __float_as_uint(As[(wr + 8 + g)*GP_A + ks*8 + c    ]);
            a[2] = __float_as_uint(As[(wr + g    )*GP_A + ks*8 + c + 4]);
            a[3] = __float_as_uint(As[(wr + 8 + g)*GP_A + ks*8 + c + 4]);
            #pragma unroll
            for (int nf = 0; nf < 8; nf++) {
                uint32_t b0 = __float_as_uint(Ws[(ks*8 + c    )*GP_W + nf*8 + g]);
                uint32_t b1 = __float_as_uint(Ws[(ks*8 + c + 4)*GP_W + nf*8 + g]);
                mma8(acc[nf], a, b0, b1);
            }
        }
        __syncthreads();
    }

    #pragma unroll
    for (int nf = 0; nf < 8; nf++) {
        int col = n0 + nf*8 + 2*c;
        float bx = fco_b[col], by = fco_b[col + 1];
        *(float2*)&out[(size_t)(row0 + wr + g    ) * EMB + col] =
            make_float2(acc[nf][0] + bx, acc[nf][1] + by);
        *(float2*)&out[(size_t)(row0 + wr + 8 + g) * EMB + col] =
            make_float2(acc[nf][2] + bx, acc[nf][3] + by);
    }
}

// ---------------------------------------------------------------------------
extern "C" void kernel_launch(void* const* d_in, const int* in_sizes, int n_in,
                              void* d_out, int out_size) {
    const float* z     = (const float*)d_in[0];
    const float* wq    = (const float*)d_in[1];
    const float* wk    = (const float*)d_in[2];
    const float* wv    = (const float*)d_in[3];
    const float* fcq_w = (const float*)d_in[4];
    const float* fcq_b = (const float*)d_in[5];
    const float* fck_w = (const float*)d_in[6];
    const float* fck_b = (const float*)d_in[7];
    const float* fcv_w = (const float*)d_in[8];
    const float* fcv_b = (const float*)d_in[9];
    const float* fco_w = (const float*)d_in[10];
    const float* fco_b = (const float*)d_in[11];
    float* out = (float*)d_out;

    static bool attr_set = false;
    if (!attr_set) {
        cudaFuncSetAttribute(k_attn_mma,    cudaFuncAttributeMaxDynamicSharedMemorySize, SMEM_ATTN);
        cudaFuncSetAttribute(k_expand,      cudaFuncAttributeMaxDynamicSharedMemorySize, SMEM_EXP);
        cudaFuncSetAttribute(k_outproj_mma, cudaFuncAttributeMaxDynamicSharedMemorySize, SMEM_GEMM);
        attr_set = true;
    }

    k_bottleneck<<<dim3(ROWS/64, 3), 256>>>(z, wq, wk, wv);
    k_expand<<<dim3(ROWS/128, 4, 3), 256, SMEM_EXP>>>(
        fcq_w, fcq_b, fck_w, fck_b, fcv_w, fcv_b);
    k_attn_mma<<<dim3(SEQ/128, NH, BB), 256, SMEM_ATTN>>>();
    k_outproj_mma<<<dim3(ROWS/128, EMB/64), 256, SMEM_GEMM>>>(fco_w, fco_b, out);
}

// round 17
// speedup vs baseline: 1.6552x; 1.0615x over previous
#include <cuda_runtime.h>
#include <math.h>
#include <stdint.h>

#define BB   4
#define SEQ  2048
#define NH   16
#define DK   64
#define EMB  1024
#define ROWS (BB*SEQ)   // 8192

// Scratch (static device globals — no runtime allocation allowed)
__device__ float g_zqkv[3][ROWS * DK];                   // bottleneck outputs
__device__ float g_qkv[3][(size_t)ROWS * EMB];           // expanded q,k,v  [b*n, H*64]
__device__ float g_att[(size_t)ROWS * EMB];              // attention output pre-proj

// ======================= helpers ===========================================
__device__ __forceinline__ uint32_t tf32cvt(float x) {
    uint32_t r; asm("cvt.rna.tf32.f32 %0, %1;" : "=r"(r) : "f"(x)); return r;
}
__device__ __forceinline__ float tf32f(float x) {
    return __uint_as_float(tf32cvt(x));
}
__device__ __forceinline__ uint32_t smem_u32(const void* p) {
    uint32_t a;
    asm("{ .reg .u64 t; cvta.to.shared.u64 t, %1; cvt.u32.u64 %0, t; }" : "=r"(a) : "l"(p));
    return a;
}
__device__ __forceinline__ void cpa16(uint32_t dst, const void* src) {
    asm volatile("cp.async.cg.shared.global [%0], [%1], 16;" :: "r"(dst), "l"(src));
}
#define CP_COMMIT() asm volatile("cp.async.commit_group;" ::: "memory")
#define CP_WAIT0()  asm volatile("cp.async.wait_group 0;" ::: "memory")
#define CP_WAIT1()  asm volatile("cp.async.wait_group 1;" ::: "memory")

// mma.sync m16n8k8 tf32 (sm_80+ feature; compiles under compute_103)
__device__ __forceinline__ void mma8(float d[4], const uint32_t a[4],
                                     uint32_t b0, uint32_t b1) {
    asm volatile("mma.sync.aligned.m16n8k8.row.col.f32.tf32.tf32.f32 "
        "{%0,%1,%2,%3}, {%4,%5,%6,%7}, {%8,%9}, {%0,%1,%2,%3};"
        : "+f"(d[0]), "+f"(d[1]), "+f"(d[2]), "+f"(d[3])
        : "r"(a[0]), "r"(a[1]), "r"(a[2]), "r"(a[3]), "r"(b0), "r"(b1));
}

// truncation-bias compensation: E[rel err of tf32 truncation] = -2^-11*ln2
#define EXP_SCALE 0.1250423312f      // 0.125 * (1 + 2^-11*ln2)  (K-path bias)
#define INV_COMP  1.00033865f        // 1 + 2^-11*ln2            (V-path bias)

// ---------------------------------------------------------------------------
// Kernel 1: fused bottleneck projections   zq/zk/zv = z @ {wq,wk,wv}  (fp32)
// ---------------------------------------------------------------------------
__global__ void k_bottleneck(const float* __restrict__ z,
                             const float* __restrict__ wq,
                             const float* __restrict__ wk,
                             const float* __restrict__ wv) {
    __shared__ __align__(16) float As[64][17];
    __shared__ __align__(16) float Bs[16][68];
    const float* w = (blockIdx.y == 0) ? wq : (blockIdx.y == 1) ? wk : wv;
    float* out = g_zqkv[blockIdx.y];

    const int tid = threadIdx.x;
    const int tx = tid & 15, ty = tid >> 4;
    const int row0 = blockIdx.x * 64;

    float acc[4][4] = {};

    for (int k0 = 0; k0 < EMB; k0 += 16) {
        {
            int r = tid >> 2, seg = tid & 3;
            float4 av = *(const float4*)(z + (size_t)(row0 + r) * EMB + k0 + seg * 4);
            As[r][seg*4+0] = av.x; As[r][seg*4+1] = av.y;
            As[r][seg*4+2] = av.z; As[r][seg*4+3] = av.w;
        }
        {
            int r = tid >> 4, seg = tid & 15;
            *(float4*)&Bs[r][seg*4] = *(const float4*)(w + (size_t)(k0 + r) * DK + seg * 4);
        }
        __syncthreads();
        #pragma unroll
        for (int k = 0; k < 16; k++) {
            float a0 = As[ty*4+0][k], a1 = As[ty*4+1][k];
            float a2 = As[ty*4+2][k], a3 = As[ty*4+3][k];
            float4 b4 = *(float4*)&Bs[k][tx*4];
            acc[0][0] += a0*b4.x; acc[0][1] += a0*b4.y; acc[0][2] += a0*b4.z; acc[0][3] += a0*b4.w;
            acc[1][0] += a1*b4.x; acc[1][1] += a1*b4.y; acc[1][2] += a1*b4.z; acc[1][3] += a1*b4.w;
            acc[2][0] += a2*b4.x; acc[2][1] += a2*b4.y; acc[2][2] += a2*b4.z; acc[2][3] += a2*b4.w;
            acc[3][0] += a3*b4.x; acc[3][1] += a3*b4.y; acc[3][2] += a3*b4.z; acc[3][3] += a3*b4.w;
        }
        __syncthreads();
    }
    #pragma unroll
    for (int i = 0; i < 4; i++)
        #pragma unroll
        for (int j = 0; j < 4; j++)
            out[(size_t)(row0 + ty*4 + i) * DK + tx*4 + j] = acc[i][j];
}

// ---------------------------------------------------------------------------
// Kernel 2: expansion  (fp32 FFMA, 8x4 microtile; A staged once over 4
// B-chunks).  grid (64, 4, 3).
// ---------------------------------------------------------------------------
#define EXP_PITCH 68
#define SMEM_EXP ((128 + 64) * EXP_PITCH * 4)

__global__ void __launch_bounds__(256, 1) k_expand(
    const float* __restrict__ fcq_w, const float* __restrict__ fcq_b,
    const float* __restrict__ fck_w, const float* __restrict__ fck_b,
    const float* __restrict__ fcv_w, const float* __restrict__ fcv_b)
{
    extern __shared__ __align__(16) float sme[];
    float* As = sme;
    float* Bs = sme + 128 * EXP_PITCH;

    const int m = blockIdx.z;
    const float* w    = (m == 0) ? fcq_w : (m == 1) ? fck_w : fcv_w;
    const float* bias = (m == 0) ? fcq_b : (m == 1) ? fck_b : fcv_b;
    const float* in = g_zqkv[m];
    float* out = g_qkv[m];

    const int tid = threadIdx.x;
    const int tx = tid & 15, ty = tid >> 4;
    const int row0 = blockIdx.x * 128;

    #pragma unroll
    for (int i = 0; i < 8; i++) {
        int idx = tid + i * 256;
        int r = idx >> 4, col = (idx & 15) * 4;
        *(float4*)&As[r*EXP_PITCH + col] = *(const float4*)(in + (size_t)(row0 + r) * DK + col);
    }
    {
        int n0 = blockIdx.y * 256;
        #pragma unroll
        for (int i = 0; i < 4; i++) {
            int idx = tid + i * 256;
            int r = idx >> 4, col = (idx & 15) * 4;
            *(float4*)&Bs[r*EXP_PITCH + col] = *(const float4*)(w + (size_t)r * EMB + n0 + col);
        }
    }
    __syncthreads();

    #pragma unroll 1
    for (int nc = 0; nc < 4; nc++) {
        const int n0 = blockIdx.y * 256 + nc * 64;

        float acc[8][4];
        #pragma unroll
        for (int i = 0; i < 8; i++)
            #pragma unroll
            for (int j = 0; j < 4; j++) acc[i][j] = 0.f;

        #pragma unroll 8
        for (int k = 0; k < 64; k++) {
            float4 b4 = *(float4*)&Bs[k*EXP_PITCH + tx*4];
            #pragma unroll
            for (int i = 0; i < 8; i++) {
                float a = As[(ty*8 + i)*EXP_PITCH + k];
                acc[i][0] += a*b4.x; acc[i][1] += a*b4.y;
                acc[i][2] += a*b4.z; acc[i][3] += a*b4.w;
            }
        }

        float4 bi = *(const float4*)(bias + n0 + tx*4);
        #pragma unroll
        for (int i = 0; i < 8; i++)
            *(float4*)&out[(size_t)(row0 + ty*8 + i) * EMB + n0 + tx*4] =
                make_float4(acc[i][0]+bi.x, acc[i][1]+bi.y, acc[i][2]+bi.z, acc[i][3]+bi.w);

        if (nc + 1 < 4) {
            __syncthreads();
            int n1 = blockIdx.y * 256 + (nc + 1) * 64;
            #pragma unroll
            for (int i = 0; i < 4; i++) {
                int idx = tid + i * 256;
                int r = idx >> 4, col = (idx & 15) * 4;
                *(float4*)&Bs[r*EXP_PITCH + col] = *(const float4*)(w + (size_t)r * EMB + n1 + col);
            }
            __syncthreads();
        }
    }
}

// ---------------------------------------------------------------------------
// Kernel 3: flash attention.  R17: NO conversion pass — K/V consumed as
// truncated tf32 with closed-form bias compensation (EXP_SCALE / INV_COMP).
// cp.async double-buffered K/V with wait_group 1 depth-2 pipeline, 2 CTAs/SM.
// ---------------------------------------------------------------------------
#define PKK 68
#define PKV 72
#define PKP 72
#define OFF_KB 0                             // 2 x [64][68]
#define OFF_V  (2*64*PKK)                    // 2 x [64][72]
#define OFF_P  (2*64*PKK + 2*64*PKV)         // [128][72]
#define SMEM_ATTN ((2*64*PKK + 2*64*PKV + 128*PKP) * 4)   // 108544 B
#define NT (SEQ/64)

__global__ void __launch_bounds__(256, 2) k_attn_mma() {
    extern __shared__ __align__(16) float sm[];
    float* Ps = sm + OFF_P;
    const uint32_t sb = smem_u32(sm);

    const int tid  = threadIdx.x;
    const int warp = tid >> 5, lane = tid & 31;
    const int g = lane >> 2, c = lane & 3;
    const int wr = warp * 16;
    const int b = blockIdx.z, h = blockIdx.y;
    const int q0 = blockIdx.x * 128;

    const float* qp = g_qkv[0] + ((size_t)(b * SEQ + q0)) * EMB + h * DK;
    const float* kp = g_qkv[1] + ((size_t)(b * SEQ)) * EMB + h * DK;
    const float* vp = g_qkv[2] + ((size_t)(b * SEQ)) * EMB + h * DK;

    const int sr = tid >> 4, sc4 = (tid & 15) * 4;

    // ---- prologue: issue K(0)+V(0); stage Q; extract qa ----
    #pragma unroll
    for (int i = 0; i < 4; i++) {
        int r = sr + i * 16;
        cpa16(sb + (uint32_t)(OFF_KB + r*PKK + sc4) * 4, kp + (size_t)r * EMB + sc4);
        cpa16(sb + (uint32_t)(OFF_V  + r*PKV + sc4) * 4, vp + (size_t)r * EMB + sc4);
    }
    CP_COMMIT();

    #pragma unroll
    for (int i = 0; i < 8; i++) {
        int idx = tid + i * 256;
        int r = idx >> 4, col = (idx & 15) * 4;
        *(float4*)&Ps[r*PKP + col] = *(const float4*)(qp + (size_t)r * EMB + col);
    }
    __syncthreads();

    uint32_t qa[8][4];
    #pragma unroll
    for (int k = 0; k < 8; k++) {
        qa[k][0] = tf32cvt(Ps[(wr + g    )*PKP + k*8 + c    ]);
        qa[k][1] = tf32cvt(Ps[(wr + 8 + g)*PKP + k*8 + c    ]);
        qa[k][2] = tf32cvt(Ps[(wr + g    )*PKP + k*8 + c + 4]);
        qa[k][3] = tf32cvt(Ps[(wr + 8 + g)*PKP + k*8 + c + 4]);
    }
    CP_WAIT0();
    __syncthreads();     // K(0)/V(0) visible; qa extraction of Ps done

    // issue tile 1 into buffer 1 (consumed next iter; stays in flight)
    {
        const float* kn = kp + (size_t)64 * EMB;
        const float* vn = vp + (size_t)64 * EMB;
        #pragma unroll
        for (int i = 0; i < 4; i++) {
            int r = sr + i * 16;
            cpa16(sb + (uint32_t)(OFF_KB + 64*PKK + r*PKK + sc4) * 4, kn + (size_t)r * EMB + sc4);
            cpa16(sb + (uint32_t)(OFF_V  + 64*PKV + r*PKV + sc4) * 4, vn + (size_t)r * EMB + sc4);
        }
        CP_COMMIT();
    }

    float oacc[8][4];
    #pragma unroll
    for (int n = 0; n < 8; n++)
        #pragma unroll
        for (int e = 0; e < 4; e++) oacc[n][e] = 0.f;
    float l0 = 0.f, l1 = 0.f;

    const int p0 = (c & 1) * 4 + (c >> 1);

    #pragma unroll 1
    for (int t = 0; t < NT; t++) {
        const float* Kcur = sm + OFF_KB + (t & 1) * 64 * PKK;
        const float* Vcur = sm + OFF_V  + (t & 1) * 64 * PKV;

        // ---- S = Q K^T  (K raw; truncation bias folded into EXP_SCALE) ----
        float sacc[8][4];
        #pragma unroll
        for (int n = 0; n < 8; n++)
            #pragma unroll
            for (int e = 0; e < 4; e++) sacc[n][e] = 0.f;
        #pragma unroll
        for (int k = 0; k < 8; k++) {
            #pragma unroll
            for (int n = 0; n < 8; n++) {
                uint32_t b0 = __float_as_uint(Kcur[(n*8 + g)*PKK + k*8 + c    ]);
                uint32_t b1 = __float_as_uint(Kcur[(n*8 + g)*PKK + k*8 + c + 4]);
                mma8(sacc[n], qa[k], b0, b1);
            }
        }

        // ---- P = exp(S * EXP_SCALE) via MUFU; RNA tf32 pair-perm store ----
        #pragma unroll
        for (int n = 0; n < 8; n++) {
            float e0 = __expf(sacc[n][0] * EXP_SCALE);
            float e1 = __expf(sacc[n][1] * EXP_SCALE);
            float e2 = __expf(sacc[n][2] * EXP_SCALE);
            float e3 = __expf(sacc[n][3] * EXP_SCALE);
            l0 += e0 + e1;
            l1 += e2 + e3;
            Ps[(wr + g    )*PKP + n*8 + p0    ] = tf32f(e0);
            Ps[(wr + g    )*PKP + n*8 + p0 + 2] = tf32f(e1);
            Ps[(wr + 8 + g)*PKP + n*8 + p0    ] = tf32f(e2);
            Ps[(wr + 8 + g)*PKP + n*8 + p0 + 2] = tf32f(e3);
        }
        __syncwarp();

        // ---- O += P V  (V raw; bias folded into INV_COMP at epilogue) ----
        #pragma unroll
        for (int k = 0; k < 8; k++) {
            float2 pA = *(const float2*)&Ps[(wr + g    )*PKP + k*8 + 2*c];
            float2 pB = *(const float2*)&Ps[(wr + 8 + g)*PKP + k*8 + 2*c];
            uint32_t a[4] = { __float_as_uint(pA.x), __float_as_uint(pB.x),
                              __float_as_uint(pA.y), __float_as_uint(pB.y) };
            #pragma unroll
            for (int n = 0; n < 8; n++) {
                uint32_t b0 = __float_as_uint(Vcur[(k*8 + c    )*PKV + n*8 + g]);
                uint32_t b1 = __float_as_uint(Vcur[(k*8 + c + 4)*PKV + n*8 + g]);
                mma8(oacc[n], a, b0, b1);
            }
        }

        // ---- pipeline turn: issue (t+2) into freed buffer, land (t+1) ----
        if (t + 1 < NT) {
            __syncthreads();   // all reads of buffers (t) complete
            if (t + 2 < NT) {
                const float* kn = kp + (size_t)(t + 2) * 64 * EMB;
                const float* vn = vp + (size_t)(t + 2) * 64 * EMB;
                uint32_t kb = (uint32_t)(OFF_KB + (t & 1) * 64 * PKK);
                uint32_t vb = (uint32_t)(OFF_V  + (t & 1) * 64 * PKV);
                #pragma unroll
                for (int i = 0; i < 4; i++) {
                    int r = sr + i * 16;
                    cpa16(sb + (kb + r*PKK + sc4) * 4, kn + (size_t)r * EMB + sc4);
                    cpa16(sb + (vb + r*PKV + sc4) * 4, vn + (size_t)r * EMB + sc4);
                }
                CP_COMMIT();
                CP_WAIT1();    // (t+1) landed; (t+2) may still be in flight
            } else {
                CP_WAIT0();    // last tile: just land (t+1)
            }
            __syncthreads();   // (t+1) visible to all warps
        }
    }

    // ---- epilogue (V truncation bias compensated via INV_COMP) ----
    l0 += __shfl_xor_sync(0xffffffffu, l0, 1);
    l0 += __shfl_xor_sync(0xffffffffu, l0, 2);
    l1 += __shfl_xor_sync(0xffffffffu, l1, 1);
    l1 += __shfl_xor_sync(0xffffffffu, l1, 2);
    float inv0 = INV_COMP / l0, inv1 = INV_COMP / l1;

    float* op0 = g_att + ((size_t)(b * SEQ + q0 + wr + g    )) * EMB + h * DK;
    float* op1 = g_att + ((size_t)(b * SEQ + q0 + wr + 8 + g)) * EMB + h * DK;
    #pragma unroll
    for (int n = 0; n < 8; n++) {
        int colb = n*8 + 2*c;
        *(float2*)&op0[colb] = make_float2(oacc[n][0] * inv0, oacc[n][1] * inv0);
        *(float2*)&op1[colb] = make_float2(oacc[n][2] * inv1, oacc[n][3] * inv1);
    }
}

// ---------------------------------------------------------------------------
// Kernel 4: output projection via tf32 mma, register-prefetch pipelined.
// ---------------------------------------------------------------------------
#define GP_A 68
#define GP_W 72
#define SMEM_GEMM ((128*GP_A + 64*GP_W) * 4)
#define KCH 16

__global__ void __launch_bounds__(256, 1) k_outproj_mma(
    const float* __restrict__ fco_w, const float* __restrict__ fco_b,
    float* __restrict__ out)
{
    extern __shared__ __align__(16) float smg[];
    float* As = smg;
    float* Ws = smg + 128 * GP_A;

    const int tid  = threadIdx.x;
    const int warp = tid >> 5, lane = tid & 31;
    const int g = lane >> 2, c = lane & 3;
    const int wr = warp * 16;
    const int row0 = blockIdx.x * 128, n0 = blockIdx.y * 64;

    const float* A = g_att;
    const float* W = fco_w;

    float4 pa[8], pw[4];

    #pragma unroll
    for (int i = 0; i < 8; i++) {
        int idx = tid + i * 256;
        int r = idx >> 4, col = (idx & 15) * 4;
        pa[i] = *(const float4*)(A + (size_t)(row0 + r) * EMB + col);
    }
    #pragma unroll
    for (int i = 0; i < 4; i++) {
        int idx = tid + i * 256;
        int r = idx >> 4, col = (idx & 15) * 4;
        pw[i] = *(const float4*)(W + (size_t)r * EMB + n0 + col);
    }

    float acc[8][4];
    #pragma unroll
    for (int nf = 0; nf < 8; nf++)
        #pragma unroll
        for (int e = 0; e < 4; e++) acc[nf][e] = 0.f;

    #pragma unroll 1
    for (int kc = 0; kc < KCH; kc++) {
        #pragma unroll
        for (int i = 0; i < 8; i++) {
            int idx = tid + i * 256;
            int r = idx >> 4, col = (idx & 15) * 4;
            *(float4*)&As[r*GP_A + col] =
                make_float4(tf32f(pa[i].x), tf32f(pa[i].y), tf32f(pa[i].z), tf32f(pa[i].w));
        }
        #pragma unroll
        for (int i = 0; i < 4; i++) {
            int idx = tid + i * 256;
            int r = idx >> 4, col = (idx & 15) * 4;
            *(float4*)&Ws[r*GP_W + col] =
                make_float4(tf32f(pw[i].x), tf32f(pw[i].y), tf32f(pw[i].z), tf32f(pw[i].w));
        }
        __syncthreads();

        if (kc + 1 < KCH) {
            const float* Ak = A + (kc + 1) * 64;
            const float* Wk = W + (size_t)((kc + 1) * 64) * EMB;
            #pragma unroll
            for (int i = 0; i < 8; i++) {
                int idx = tid + i * 256;
                int r = idx >> 4, col = (idx & 15) * 4;
                pa[i] = *(const float4*)(Ak + (size_t)(row0 + r) * EMB + col);
            }
            #pragma unroll
            for (int i = 0; i < 4; i++) {
                int idx = tid + i * 256;
                int r = idx >> 4, col = (idx & 15) * 4;
                pw[i] = *(const float4*)(Wk + (size_t)r * EMB + n0 + col);
            }
        }

        #pragma unroll
        for (int ks = 0; ks < 8; ks++) {
            uint32_t a[4];
            a[0] = __float_as_uint(As[(wr + g    )*GP_A + ks*8 + c    ]);
            a[1] = __float_as_uint(As[(wr + 8 + g)*GP_A + ks*8 + c    ]);
            a[2] = __float_as_uint(As[(wr + g    )*GP_A + ks*8 + c + 4]);
            a[3] = __float_as_uint(As[(wr + 8 + g)*GP_A + ks*8 + c + 4]);
            #pragma unroll
            for (int nf = 0; nf < 8; nf++) {
                uint32_t b0 = __float_as_uint(Ws[(ks*8 + c    )*GP_W + nf*8 + g]);
                uint32_t b1 = __float_as_uint(Ws[(ks*8 + c + 4)*GP_W + nf*8 + g]);
                mma8(acc[nf], a, b0, b1);
            }
        }
        __syncthreads();
    }

    #pragma unroll
    for (int nf = 0; nf < 8; nf++) {
        int col = n0 + nf*8 + 2*c;
        float bx = fco_b[col], by = fco_b[col + 1];
        *(float2*)&out[(size_t)(row0 + wr + g    ) * EMB + col] =
            make_float2(acc[nf][0] + bx, acc[nf][1] + by);
        *(float2*)&out[(size_t)(row0 + wr + 8 + g) * EMB + col] =
            make_float2(acc[nf][2] + bx, acc[nf][3] + by);
    }
}

// ---------------------------------------------------------------------------
extern "C" void kernel_launch(void* const* d_in, const int* in_sizes, int n_in,
                              void* d_out, int out_size) {
    const float* z     = (const float*)d_in[0];
    const float* wq    = (const float*)d_in[1];
    const float* wk    = (const float*)d_in[2];
    const float* wv    = (const float*)d_in[3];
    const float* fcq_w = (const float*)d_in[4];
    const float* fcq_b = (const float*)d_in[5];
    const float* fck_w = (const float*)d_in[6];
    const float* fck_b = (const float*)d_in[7];
    const float* fcv_w = (const float*)d_in[8];
    const float* fcv_b = (const float*)d_in[9];
    const float* fco_w = (const float*)d_in[10];
    const float* fco_b = (const float*)d_in[11];
    float* out = (float*)d_out;

    static bool attr_set = false;
    if (!attr_set) {
        cudaFuncSetAttribute(k_attn_mma,    cudaFuncAttributeMaxDynamicSharedMemorySize, SMEM_ATTN);
        cudaFuncSetAttribute(k_expand,      cudaFuncAttributeMaxDynamicSharedMemorySize, SMEM_EXP);
        cudaFuncSetAttribute(k_outproj_mma, cudaFuncAttributeMaxDynamicSharedMemorySize, SMEM_GEMM);
        attr_set = true;
    }

    k_bottleneck<<<dim3(ROWS/64, 3), 256>>>(z, wq, wk, wv);
    k_expand<<<dim3(ROWS/128, 4, 3), 256, SMEM_EXP>>>(
        fcq_w, fcq_b, fck_w, fck_b, fcv_w, fcv_b);
    k_attn_mma<<<dim3(SEQ/128, NH, BB), 256, SMEM_ATTN>>>();
    k_outproj_mma<<<dim3(ROWS/128, EMB/64), 256, SMEM_GEMM>>>(fco_w, fco_b, out);
}